// round 11
// baseline (speedup 1.0000x reference)
#include <cuda_runtime.h>
#include <cuda_bf16.h>
#include <math.h>
#include <stdint.h>

#define B_TOT   4096
#define NWIN    64
#define NTOK    49
#define DIM     192
#define NHEAD   6
#define HDIM    32
#define M_ROWS  (B_TOT * NTOK)     /* 200704 */
#define QKV_N   576
#define NN      (NTOK * NTOK)      /* 2401 */

// Scratch (no cudaMalloc allowed); referenced directly from kernels so that
// kernel_launch contains ONLY kernel launches (trivially graph-capturable).
__device__ float g_qkv[(size_t)M_ROWS * QKV_N];          // 462 MB
__device__ float g_ctx[(size_t)M_ROWS * DIM];            // 154 MB
__device__ float g_bm[(size_t)NWIN * NHEAD * NN];        // 3.7 MB bias+mask

// ---------------------------------------------------------------------------
// Precompute bm[(mb*NHEAD+h)][e] = rpb[rel_idx[e]*NHEAD+h] + mask[mb][e]
// ---------------------------------------------------------------------------
__global__ __launch_bounds__(256)
void bm_kernel(const float* __restrict__ mask,
               const float* __restrict__ rpb_table,
               const int*   __restrict__ rel_idx)
{
    const int mb = blockIdx.x / NHEAD;
    const int h  = blockIdx.x % NHEAD;
    float* dst = &g_bm[(size_t)blockIdx.x * NN];
    const float* msk = &mask[(size_t)mb * NN];
    for (int e = threadIdx.x; e < NN; e += 256)
        dst[e] = rpb_table[rel_idx[e] * NHEAD + h] + msk[e];
}

// ---------------------------------------------------------------------------
// bf16x3 tensor-core GEMM with ldmatrix fragment loads.
// C[M,N] = A[M,K] @ W^T + bias, W row-major [N,K].
// BM=128, BN=64, BK=16, 256 threads (8 warps, 4x2 grid of 32x32 warp tiles).
// ---------------------------------------------------------------------------
__device__ __forceinline__ uint32_t pack_bf16x2(float x, float y) {
    __nv_bfloat162 t = __floats2bfloat162_rn(x, y);   // x -> low 16 bits
    return *reinterpret_cast<uint32_t*>(&t);
}

__device__ __forceinline__ void mma_bf16(float* d, const uint32_t* a, const uint32_t* b) {
    asm volatile(
        "mma.sync.aligned.m16n8k16.row.col.f32.bf16.bf16.f32 "
        "{%0,%1,%2,%3}, {%4,%5,%6,%7}, {%8,%9}, {%0,%1,%2,%3};"
        : "+f"(d[0]), "+f"(d[1]), "+f"(d[2]), "+f"(d[3])
        : "r"(a[0]), "r"(a[1]), "r"(a[2]), "r"(a[3]), "r"(b[0]), "r"(b[1]));
}

__device__ __forceinline__ void ldsm_x4(uint32_t* r, uint32_t saddr) {
    asm volatile(
        "ldmatrix.sync.aligned.m8n8.x4.shared.b16 {%0,%1,%2,%3}, [%4];"
        : "=r"(r[0]), "=r"(r[1]), "=r"(r[2]), "=r"(r[3]) : "r"(saddr));
}

#define SW 12   /* smem row stride in 32-bit words (8 data + 4 pad): conflict-free */

__device__ __forceinline__
void gemm_bf16x3_body(const float* __restrict__ A,
                      const float* __restrict__ W,
                      const float* __restrict__ bias,
                      float* __restrict__ C,
                      int M, int N, int K)
{
    __shared__ uint32_t Ah[128 * SW];
    __shared__ uint32_t Al[128 * SW];
    __shared__ uint32_t Bh[64 * SW];
    __shared__ uint32_t Bl[64 * SW];

    const int tid  = threadIdx.x;
    const int warp = tid >> 5;
    const int lane = tid & 31;
    const int wm   = warp >> 1;        // 0..3 -> m offset wm*32
    const int wn   = warp & 1;         // 0..1 -> n offset wn*32
    const int lr   = lane >> 2;        // 0..7
    const int lc   = lane & 3;         // 0..3
    const int r0   = blockIdx.y * 128;
    const int c0   = blockIdx.x * 64;

    // global load indices
    const int ar = tid >> 1;           // A row 0..127
    const int ac = (tid & 1) * 8;      // A col 0 or 8
    const int br = tid >> 2;           // B row 0..63
    const int bc = (tid & 3) * 4;      // B col 0,4,8,12

    const float* Ag = &A[(size_t)(r0 + ar) * K + ac];
    const float* Wg = &W[(size_t)(c0 + br) * K + bc];

    // ldmatrix lane addressing (precomputed, bytes via cvta)
    // A (m16n16 frag): lanes 0-15 -> rows, lanes 16-31 -> 16B segment 1
    const int a_lrow = wm * 32 + (lane & 15);
    const int a_lseg = (lane >> 4) * 4;          // word offset 0 or 4
    const uint32_t aAddrH = (uint32_t)__cvta_generic_to_shared(
        &Ah[a_lrow * SW + a_lseg]);
    const uint32_t aAddrL = (uint32_t)__cvta_generic_to_shared(
        &Al[a_lrow * SW + a_lseg]);
    // B (two 8x16 n-tiles per x4): groups of 8 lanes ->
    //   g0: ntA seg0, g1: ntA seg1, g2: ntB seg0, g3: ntB seg1
    const int b_lrow = wn * 32 + ((lane >> 4) & 1) * 8 + (lane & 7);
    const int b_lseg = ((lane >> 3) & 1) * 4;
    const uint32_t bAddrH = (uint32_t)__cvta_generic_to_shared(
        &Bh[b_lrow * SW + b_lseg]);
    const uint32_t bAddrL = (uint32_t)__cvta_generic_to_shared(
        &Bl[b_lrow * SW + b_lseg]);

    float acc[2][4][4];
#pragma unroll
    for (int mt = 0; mt < 2; mt++)
#pragma unroll
        for (int nt = 0; nt < 4; nt++)
#pragma unroll
            for (int r = 0; r < 4; r++) acc[mt][nt][r] = 0.f;

    // prologue prefetch
    float ap[8], bp[4];
    {
        const float4 a0 = *reinterpret_cast<const float4*>(Ag);
        const float4 a1 = *reinterpret_cast<const float4*>(Ag + 4);
        ap[0]=a0.x; ap[1]=a0.y; ap[2]=a0.z; ap[3]=a0.w;
        ap[4]=a1.x; ap[5]=a1.y; ap[6]=a1.z; ap[7]=a1.w;
        const float4 b0 = *reinterpret_cast<const float4*>(Wg);
        bp[0]=b0.x; bp[1]=b0.y; bp[2]=b0.z; bp[3]=b0.w;
    }

    for (int k0 = 0; k0 < K; k0 += 16) {
        // split hi/lo, pack bf16x2, store to smem
#pragma unroll
        for (int i = 0; i < 4; i++) {
            const float f0 = ap[2 * i], f1 = ap[2 * i + 1];
            const float h0 = __bfloat162float(__float2bfloat16_rn(f0));
            const float h1 = __bfloat162float(__float2bfloat16_rn(f1));
            Ah[ar * SW + ac / 2 + i] = pack_bf16x2(h0, h1);
            Al[ar * SW + ac / 2 + i] = pack_bf16x2(f0 - h0, f1 - h1);
        }
#pragma unroll
        for (int i = 0; i < 2; i++) {
            const float f0 = bp[2 * i], f1 = bp[2 * i + 1];
            const float h0 = __bfloat162float(__float2bfloat16_rn(f0));
            const float h1 = __bfloat162float(__float2bfloat16_rn(f1));
            Bh[br * SW + bc / 2 + i] = pack_bf16x2(h0, h1);
            Bl[br * SW + bc / 2 + i] = pack_bf16x2(f0 - h0, f1 - h1);
        }
        __syncthreads();

        // prefetch next tile
        if (k0 + 16 < K) {
            const float4 a0 = *reinterpret_cast<const float4*>(Ag + k0 + 16);
            const float4 a1 = *reinterpret_cast<const float4*>(Ag + k0 + 20);
            ap[0]=a0.x; ap[1]=a0.y; ap[2]=a0.z; ap[3]=a0.w;
            ap[4]=a1.x; ap[5]=a1.y; ap[6]=a1.z; ap[7]=a1.w;
            const float4 b0 = *reinterpret_cast<const float4*>(Wg + k0 + 16);
            bp[0]=b0.x; bp[1]=b0.y; bp[2]=b0.z; bp[3]=b0.w;
        }

        // fragment loads via ldmatrix: 4 + 4 LDSM.x4 total
        uint32_t ah[2][4], al[2][4], bhp[2][4], blp[2][4];
#pragma unroll
        for (int mt = 0; mt < 2; mt++) {
            ldsm_x4(ah[mt], aAddrH + mt * 16 * SW * 4);
            ldsm_x4(al[mt], aAddrL + mt * 16 * SW * 4);
        }
#pragma unroll
        for (int p = 0; p < 2; p++) {
            ldsm_x4(bhp[p], bAddrH + p * 16 * SW * 4);
            ldsm_x4(blp[p], bAddrL + p * 16 * SW * 4);
        }

#pragma unroll
        for (int mt = 0; mt < 2; mt++)
#pragma unroll
            for (int nt = 0; nt < 4; nt++) {
                const uint32_t bh2[2] = {bhp[nt >> 1][(nt & 1) * 2],
                                         bhp[nt >> 1][(nt & 1) * 2 + 1]};
                const uint32_t bl2[2] = {blp[nt >> 1][(nt & 1) * 2],
                                         blp[nt >> 1][(nt & 1) * 2 + 1]};
                mma_bf16(acc[mt][nt], ah[mt], bl2);   // hi*lo
                mma_bf16(acc[mt][nt], al[mt], bh2);   // lo*hi
                mma_bf16(acc[mt][nt], ah[mt], bh2);   // hi*hi
            }
        __syncthreads();
    }

    // epilogue
#pragma unroll
    for (int mt = 0; mt < 2; mt++) {
        const int row = r0 + wm * 32 + mt * 16 + lr;
#pragma unroll
        for (int nt = 0; nt < 4; nt++) {
            const int col = c0 + wn * 32 + nt * 8 + lc * 2;
            const float b0v = bias[col], b1v = bias[col + 1];
            float2 s0, s1;
            s0.x = acc[mt][nt][0] + b0v; s0.y = acc[mt][nt][1] + b1v;
            s1.x = acc[mt][nt][2] + b0v; s1.y = acc[mt][nt][3] + b1v;
            *reinterpret_cast<float2*>(&C[(size_t)row * N + col])       = s0;
            *reinterpret_cast<float2*>(&C[(size_t)(row + 8) * N + col]) = s1;
        }
    }
}

// Wrappers referencing __device__ globals directly (no symbol lookups on host)
__global__ __launch_bounds__(256)
void qkv_gemm_kernel(const float* __restrict__ x,
                     const float* __restrict__ qkv_w,
                     const float* __restrict__ qkv_b)
{
    gemm_bf16x3_body(x, qkv_w, qkv_b, g_qkv, M_ROWS, QKV_N, DIM);
}

__global__ __launch_bounds__(256)
void proj_gemm_kernel(const float* __restrict__ proj_w,
                      const float* __restrict__ proj_b,
                      float* __restrict__ out)
{
    gemm_bf16x3_body(g_ctx, proj_w, proj_b, out, M_ROWS, DIM, DIM);
}

// ---------------------------------------------------------------------------
// Fused attention (proven): one block per (window b, head h).
// ---------------------------------------------------------------------------
#define QPAD 52

__global__ __launch_bounds__(256)
void attn_kernel(float* __restrict__ attn_out, int write_attn)
{
    const int bh = blockIdx.x;
    const int b  = bh / NHEAD;
    const int h  = bh % NHEAD;
    const int tid = threadIdx.x;
    const int mb = b % NWIN;

    __shared__ float4 qs[QPAD * 9];
    __shared__ float4 ksT4[8 * QPAD];
    __shared__ float4 vs[NTOK * 8];
    __shared__ float  s[NTOK * 56];

    const size_t row0 = (size_t)b * NTOK;
    const int qoff = h * HDIM;
    const float scale = 0.1767766952966369f;

    for (int e = tid; e < QPAD * 8; e += 256) {
        const int i = e >> 3, c = e & 7;
        if (i < NTOK) {
            const size_t base = (row0 + i) * QKV_N + qoff + c * 4;
            float4 qv = *reinterpret_cast<const float4*>(&g_qkv[base]);
            qv.x *= scale; qv.y *= scale; qv.z *= scale; qv.w *= scale;
            qs[i * 9 + c] = qv;
            ksT4[c * QPAD + i] = *reinterpret_cast<const float4*>(&g_qkv[base + DIM]);
            vs[i * 8 + c] = *reinterpret_cast<const float4*>(&g_qkv[base + 2 * DIM]);
        } else {
            const float4 z = make_float4(0.f, 0.f, 0.f, 0.f);
            qs[i * 9 + c] = z;
            ksT4[c * QPAD + i] = z;
        }
    }
    __syncthreads();

    const float* bm = &g_bm[(size_t)(mb * NHEAD + h) * NN];
    if (tid < 169) {
        const int ti = tid / 13, tj = tid % 13;
        const int i0 = ti * 4, j0 = tj * 4;
        float acc[4][4];
#pragma unroll
        for (int u = 0; u < 4; u++)
#pragma unroll
            for (int v = 0; v < 4; v++) acc[u][v] = 0.f;
#pragma unroll
        for (int c = 0; c < 8; c++) {
            float4 qv[4], kv[4];
#pragma unroll
            for (int u = 0; u < 4; u++) qv[u] = qs[(i0 + u) * 9 + c];
#pragma unroll
            for (int v = 0; v < 4; v++) kv[v] = ksT4[c * QPAD + j0 + v];
#pragma unroll
            for (int u = 0; u < 4; u++)
#pragma unroll
                for (int v = 0; v < 4; v++)
                    acc[u][v] += qv[u].x * kv[v].x + qv[u].y * kv[v].y
                               + qv[u].z * kv[v].z + qv[u].w * kv[v].w;
        }
#pragma unroll
        for (int u = 0; u < 4; u++) {
            const int i = i0 + u;
            if (i < NTOK) {
#pragma unroll
                for (int v = 0; v < 4; v++) {
                    const int j = j0 + v;
                    if (j < NTOK)
                        s[i * 56 + j] = acc[u][v] + bm[i * NTOK + j];
                }
            }
        }
    }
    __syncthreads();

    {
        const int row = tid >> 2;
        const int q4  = tid & 3;
        const bool act = (row < NTOK);
        float* rowp = &s[(act ? row : 0) * 56];
        float mx = -1e30f;
        if (act) for (int j = q4; j < NTOK; j += 4) mx = fmaxf(mx, rowp[j]);
        mx = fmaxf(mx, __shfl_xor_sync(0xffffffffu, mx, 1));
        mx = fmaxf(mx, __shfl_xor_sync(0xffffffffu, mx, 2));
        float sum = 0.f;
        if (act) {
            for (int j = q4; j < NTOK; j += 4) {
                const float ev = __expf(rowp[j] - mx);
                rowp[j] = ev;
                sum += ev;
            }
        }
        sum += __shfl_xor_sync(0xffffffffu, sum, 1);
        sum += __shfl_xor_sync(0xffffffffu, sum, 2);
        if (act) {
            const float inv = 1.f / sum;
            for (int j = q4; j < NTOK; j += 4) rowp[j] *= inv;
        }
    }
    __syncthreads();

    if (write_attn) {
        float* ao = &attn_out[(size_t)bh * NN];
        for (int e = tid; e < NN; e += 256) {
            const int i = e / NTOK, j = e - i * NTOK;
            ao[e] = s[i * 56 + j];
        }
    }

    if (tid < 200) {
        const int ip = tid >> 3, d4 = tid & 7;
        const int i0 = ip * 2;
        float4 a0 = make_float4(0.f, 0.f, 0.f, 0.f);
        float4 a1 = make_float4(0.f, 0.f, 0.f, 0.f);
        const float* s0 = &s[i0 * 56];
        const bool two = (i0 + 1 < NTOK);
#pragma unroll
        for (int j = 0; j < NTOK; j++) {
            const float4 vv = vs[j * 8 + d4];
            const float p0 = s0[j];
            a0.x += p0 * vv.x; a0.y += p0 * vv.y;
            a0.z += p0 * vv.z; a0.w += p0 * vv.w;
            const float p1 = two ? s0[56 + j] : 0.f;
            a1.x += p1 * vv.x; a1.y += p1 * vv.y;
            a1.z += p1 * vv.z; a1.w += p1 * vv.w;
        }
        *reinterpret_cast<float4*>(&g_ctx[(row0 + i0) * DIM + qoff + d4 * 4]) = a0;
        if (two)
            *reinterpret_cast<float4*>(&g_ctx[(row0 + i0 + 1) * DIM + qoff + d4 * 4]) = a1;
    }
}

extern "C" void kernel_launch(void* const* d_in, const int* in_sizes, int n_in,
                              void* d_out, int out_size)
{
    const float* x      = (const float*)d_in[0];
    const float* mask   = (const float*)d_in[1];
    const float* qkv_w  = (const float*)d_in[2];
    const float* qkv_b  = (const float*)d_in[3];
    const float* proj_w = (const float*)d_in[4];
    const float* proj_b = (const float*)d_in[5];
    const float* rpb    = (const float*)d_in[6];
    const int*   relidx = (const int*)d_in[7];
    float* out = (float*)d_out;

    const long out_elems  = (long)M_ROWS * DIM;                 // 38,535,168
    const long attn_elems = (long)B_TOT * NHEAD * NN;           // 59,006,976
    const int write_attn = ((long)out_size >= out_elems + attn_elems) ? 1 : 0;
    float* attn_out = out + out_elems;

    // 0) bias+mask table
    bm_kernel<<<NWIN * NHEAD, 256>>>(mask, rpb, relidx);

    // 1) QKV GEMM: [200704,192] @ [192,576] (bf16x3 tensor cores + ldmatrix)
    qkv_gemm_kernel<<<dim3(QKV_N / 64, M_ROWS / 128), 256>>>(x, qkv_w, qkv_b);

    // 2) fused window attention
    attn_kernel<<<B_TOT * NHEAD, 256>>>(attn_out, write_attn);

    // 3) projection: [200704,192] @ [192,192] (bf16x3 tensor cores + ldmatrix)
    proj_gemm_kernel<<<dim3(DIM / 64, M_ROWS / 128), 256>>>(proj_w, proj_b, out);
}

// round 12
// speedup vs baseline: 1.0283x; 1.0283x over previous
#include <cuda_runtime.h>
#include <cuda_bf16.h>
#include <math.h>
#include <stdint.h>

#define B_TOT   4096
#define NWIN    64
#define NTOK    49
#define DIM     192
#define NHEAD   6
#define HDIM    32
#define M_ROWS  (B_TOT * NTOK)     /* 200704 */
#define QKV_N   576
#define NN      (NTOK * NTOK)      /* 2401 */

// Scratch (no cudaMalloc allowed); referenced directly from kernels so that
// kernel_launch contains ONLY kernel launches (trivially graph-capturable).
__device__ float g_qkv[(size_t)M_ROWS * QKV_N];          // 462 MB
__device__ float g_ctx[(size_t)M_ROWS * DIM];            // 154 MB
__device__ float g_bm[(size_t)NWIN * NHEAD * NN];        // 3.7 MB bias+mask

// ---------------------------------------------------------------------------
// Precompute bm[(mb*NHEAD+h)][e] = rpb[rel_idx[e]*NHEAD+h] + mask[mb][e]
// ---------------------------------------------------------------------------
__global__ __launch_bounds__(256)
void bm_kernel(const float* __restrict__ mask,
               const float* __restrict__ rpb_table,
               const int*   __restrict__ rel_idx)
{
    const int mb = blockIdx.x / NHEAD;
    const int h  = blockIdx.x % NHEAD;
    float* dst = &g_bm[(size_t)blockIdx.x * NN];
    const float* msk = &mask[(size_t)mb * NN];
    for (int e = threadIdx.x; e < NN; e += 256)
        dst[e] = rpb_table[rel_idx[e] * NHEAD + h] + msk[e];
}

// ---------------------------------------------------------------------------
// bf16x3 tensor-core GEMM, double-buffered smem, ONE barrier per k-iter.
// C[M,N] = A[M,K] @ W^T + bias, W row-major [N,K].
// BM=128, BN=64, BK=16, 256 threads (8 warps, 4x2 grid of 32x32 warp tiles).
// Scalar LDS fragment loads (R9-proven; ldmatrix variant regressed).
// ---------------------------------------------------------------------------
__device__ __forceinline__ uint32_t pack_bf16x2(float x, float y) {
    __nv_bfloat162 t = __floats2bfloat162_rn(x, y);   // x -> low 16 bits
    return *reinterpret_cast<uint32_t*>(&t);
}

__device__ __forceinline__ void mma_bf16(float* d, const uint32_t* a, const uint32_t* b) {
    asm volatile(
        "mma.sync.aligned.m16n8k16.row.col.f32.bf16.bf16.f32 "
        "{%0,%1,%2,%3}, {%4,%5,%6,%7}, {%8,%9}, {%0,%1,%2,%3};"
        : "+f"(d[0]), "+f"(d[1]), "+f"(d[2]), "+f"(d[3])
        : "r"(a[0]), "r"(a[1]), "r"(a[2]), "r"(a[3]), "r"(b[0]), "r"(b[1]));
}

#define SW 12   /* smem row stride in 32-bit words (8 data + 4 pad): conflict-free */

__device__ __forceinline__
void gemm_bf16x3_body(const float* __restrict__ A,
                      const float* __restrict__ W,
                      const float* __restrict__ bias,
                      float* __restrict__ C,
                      int M, int N, int K)
{
    __shared__ uint32_t Ah[2][128 * SW];
    __shared__ uint32_t Al[2][128 * SW];
    __shared__ uint32_t Bh[2][64 * SW];
    __shared__ uint32_t Bl[2][64 * SW];

    const int tid  = threadIdx.x;
    const int warp = tid >> 5;
    const int lane = tid & 31;
    const int wm   = warp >> 1;        // 0..3 -> m offset wm*32
    const int wn   = warp & 1;         // 0..1 -> n offset wn*32
    const int lr   = lane >> 2;        // 0..7
    const int lc   = lane & 3;         // 0..3
    const int r0   = blockIdx.y * 128;
    const int c0   = blockIdx.x * 64;

    // global load indices
    const int ar = tid >> 1;           // A row 0..127
    const int ac = (tid & 1) * 8;      // A col 0 or 8
    const int br = tid >> 2;           // B row 0..63
    const int bc = (tid & 3) * 4;      // B col 0,4,8,12

    const float* Ag = &A[(size_t)(r0 + ar) * K + ac];
    const float* Wg = &W[(size_t)(c0 + br) * K + bc];

    float acc[2][4][4];
#pragma unroll
    for (int mt = 0; mt < 2; mt++)
#pragma unroll
        for (int nt = 0; nt < 4; nt++)
#pragma unroll
            for (int r = 0; r < 4; r++) acc[mt][nt][r] = 0.f;

    // prologue prefetch (tile 0)
    float ap[8], bp[4];
    {
        const float4 a0 = *reinterpret_cast<const float4*>(Ag);
        const float4 a1 = *reinterpret_cast<const float4*>(Ag + 4);
        ap[0]=a0.x; ap[1]=a0.y; ap[2]=a0.z; ap[3]=a0.w;
        ap[4]=a1.x; ap[5]=a1.y; ap[6]=a1.z; ap[7]=a1.w;
        const float4 b0 = *reinterpret_cast<const float4*>(Wg);
        bp[0]=b0.x; bp[1]=b0.y; bp[2]=b0.z; bp[3]=b0.w;
    }

    int cur = 0;
    for (int k0 = 0; k0 < K; k0 += 16) {
        // split hi/lo, pack bf16x2, store to smem buffer `cur`
#pragma unroll
        for (int i = 0; i < 4; i++) {
            const float f0 = ap[2 * i], f1 = ap[2 * i + 1];
            const float h0 = __bfloat162float(__float2bfloat16_rn(f0));
            const float h1 = __bfloat162float(__float2bfloat16_rn(f1));
            Ah[cur][ar * SW + ac / 2 + i] = pack_bf16x2(h0, h1);
            Al[cur][ar * SW + ac / 2 + i] = pack_bf16x2(f0 - h0, f1 - h1);
        }
#pragma unroll
        for (int i = 0; i < 2; i++) {
            const float f0 = bp[2 * i], f1 = bp[2 * i + 1];
            const float h0 = __bfloat162float(__float2bfloat16_rn(f0));
            const float h1 = __bfloat162float(__float2bfloat16_rn(f1));
            Bh[cur][br * SW + bc / 2 + i] = pack_bf16x2(h0, h1);
            Bl[cur][br * SW + bc / 2 + i] = pack_bf16x2(f0 - h0, f1 - h1);
        }
        __syncthreads();   // the ONLY barrier per iteration

        // prefetch next tile while MMAs below execute
        if (k0 + 16 < K) {
            const float4 a0 = *reinterpret_cast<const float4*>(Ag + k0 + 16);
            const float4 a1 = *reinterpret_cast<const float4*>(Ag + k0 + 20);
            ap[0]=a0.x; ap[1]=a0.y; ap[2]=a0.z; ap[3]=a0.w;
            ap[4]=a1.x; ap[5]=a1.y; ap[6]=a1.z; ap[7]=a1.w;
            const float4 b0 = *reinterpret_cast<const float4*>(Wg + k0 + 16);
            bp[0]=b0.x; bp[1]=b0.y; bp[2]=b0.z; bp[3]=b0.w;
        }

        // fragment loads (scalar LDS) + 24 MMAs from buffer `cur`
        uint32_t ah[2][4], al[2][4], bh[4][2], bl[4][2];
#pragma unroll
        for (int mt = 0; mt < 2; mt++) {
            const int base = (wm * 32 + mt * 16 + lr) * SW + lc;
            ah[mt][0] = Ah[cur][base];
            ah[mt][1] = Ah[cur][base + 8 * SW];
            ah[mt][2] = Ah[cur][base + 4];
            ah[mt][3] = Ah[cur][base + 8 * SW + 4];
            al[mt][0] = Al[cur][base];
            al[mt][1] = Al[cur][base + 8 * SW];
            al[mt][2] = Al[cur][base + 4];
            al[mt][3] = Al[cur][base + 8 * SW + 4];
        }
#pragma unroll
        for (int nt = 0; nt < 4; nt++) {
            const int nb = (wn * 32 + nt * 8 + lr) * SW + lc;
            bh[nt][0] = Bh[cur][nb];
            bh[nt][1] = Bh[cur][nb + 4];
            bl[nt][0] = Bl[cur][nb];
            bl[nt][1] = Bl[cur][nb + 4];
        }
#pragma unroll
        for (int mt = 0; mt < 2; mt++)
#pragma unroll
            for (int nt = 0; nt < 4; nt++) {
                mma_bf16(acc[mt][nt], ah[mt], bl[nt]);   // hi*lo
                mma_bf16(acc[mt][nt], al[mt], bh[nt]);   // lo*hi
                mma_bf16(acc[mt][nt], ah[mt], bh[nt]);   // hi*hi
            }
        cur ^= 1;
    }

    // epilogue
#pragma unroll
    for (int mt = 0; mt < 2; mt++) {
        const int row = r0 + wm * 32 + mt * 16 + lr;
#pragma unroll
        for (int nt = 0; nt < 4; nt++) {
            const int col = c0 + wn * 32 + nt * 8 + lc * 2;
            const float b0v = bias[col], b1v = bias[col + 1];
            float2 s0, s1;
            s0.x = acc[mt][nt][0] + b0v; s0.y = acc[mt][nt][1] + b1v;
            s1.x = acc[mt][nt][2] + b0v; s1.y = acc[mt][nt][3] + b1v;
            *reinterpret_cast<float2*>(&C[(size_t)row * N + col])       = s0;
            *reinterpret_cast<float2*>(&C[(size_t)(row + 8) * N + col]) = s1;
        }
    }
}

// Wrappers referencing __device__ globals directly (no symbol lookups on host)
__global__ __launch_bounds__(256)
void qkv_gemm_kernel(const float* __restrict__ x,
                     const float* __restrict__ qkv_w,
                     const float* __restrict__ qkv_b)
{
    gemm_bf16x3_body(x, qkv_w, qkv_b, g_qkv, M_ROWS, QKV_N, DIM);
}

__global__ __launch_bounds__(256)
void proj_gemm_kernel(const float* __restrict__ proj_w,
                      const float* __restrict__ proj_b,
                      float* __restrict__ out)
{
    gemm_bf16x3_body(g_ctx, proj_w, proj_b, out, M_ROWS, DIM, DIM);
}

// ---------------------------------------------------------------------------
// Fused attention (proven): one block per (window b, head h).
// ---------------------------------------------------------------------------
#define QPAD 52

__global__ __launch_bounds__(256)
void attn_kernel(float* __restrict__ attn_out, int write_attn)
{
    const int bh = blockIdx.x;
    const int b  = bh / NHEAD;
    const int h  = bh % NHEAD;
    const int tid = threadIdx.x;
    const int mb = b % NWIN;

    __shared__ float4 qs[QPAD * 9];
    __shared__ float4 ksT4[8 * QPAD];
    __shared__ float4 vs[NTOK * 8];
    __shared__ float  s[NTOK * 56];

    const size_t row0 = (size_t)b * NTOK;
    const int qoff = h * HDIM;
    const float scale = 0.1767766952966369f;

    for (int e = tid; e < QPAD * 8; e += 256) {
        const int i = e >> 3, c = e & 7;
        if (i < NTOK) {
            const size_t base = (row0 + i) * QKV_N + qoff + c * 4;
            float4 qv = *reinterpret_cast<const float4*>(&g_qkv[base]);
            qv.x *= scale; qv.y *= scale; qv.z *= scale; qv.w *= scale;
            qs[i * 9 + c] = qv;
            ksT4[c * QPAD + i] = *reinterpret_cast<const float4*>(&g_qkv[base + DIM]);
            vs[i * 8 + c] = *reinterpret_cast<const float4*>(&g_qkv[base + 2 * DIM]);
        } else {
            const float4 z = make_float4(0.f, 0.f, 0.f, 0.f);
            qs[i * 9 + c] = z;
            ksT4[c * QPAD + i] = z;
        }
    }
    __syncthreads();

    const float* bm = &g_bm[(size_t)(mb * NHEAD + h) * NN];
    if (tid < 169) {
        const int ti = tid / 13, tj = tid % 13;
        const int i0 = ti * 4, j0 = tj * 4;
        float acc[4][4];
#pragma unroll
        for (int u = 0; u < 4; u++)
#pragma unroll
            for (int v = 0; v < 4; v++) acc[u][v] = 0.f;
#pragma unroll
        for (int c = 0; c < 8; c++) {
            float4 qv[4], kv[4];
#pragma unroll
            for (int u = 0; u < 4; u++) qv[u] = qs[(i0 + u) * 9 + c];
#pragma unroll
            for (int v = 0; v < 4; v++) kv[v] = ksT4[c * QPAD + j0 + v];
#pragma unroll
            for (int u = 0; u < 4; u++)
#pragma unroll
                for (int v = 0; v < 4; v++)
                    acc[u][v] += qv[u].x * kv[v].x + qv[u].y * kv[v].y
                               + qv[u].z * kv[v].z + qv[u].w * kv[v].w;
        }
#pragma unroll
        for (int u = 0; u < 4; u++) {
            const int i = i0 + u;
            if (i < NTOK) {
#pragma unroll
                for (int v = 0; v < 4; v++) {
                    const int j = j0 + v;
                    if (j < NTOK)
                        s[i * 56 + j] = acc[u][v] + bm[i * NTOK + j];
                }
            }
        }
    }
    __syncthreads();

    {
        const int row = tid >> 2;
        const int q4  = tid & 3;
        const bool act = (row < NTOK);
        float* rowp = &s[(act ? row : 0) * 56];
        float mx = -1e30f;
        if (act) for (int j = q4; j < NTOK; j += 4) mx = fmaxf(mx, rowp[j]);
        mx = fmaxf(mx, __shfl_xor_sync(0xffffffffu, mx, 1));
        mx = fmaxf(mx, __shfl_xor_sync(0xffffffffu, mx, 2));
        float sum = 0.f;
        if (act) {
            for (int j = q4; j < NTOK; j += 4) {
                const float ev = __expf(rowp[j] - mx);
                rowp[j] = ev;
                sum += ev;
            }
        }
        sum += __shfl_xor_sync(0xffffffffu, sum, 1);
        sum += __shfl_xor_sync(0xffffffffu, sum, 2);
        if (act) {
            const float inv = 1.f / sum;
            for (int j = q4; j < NTOK; j += 4) rowp[j] *= inv;
        }
    }
    __syncthreads();

    if (write_attn) {
        float* ao = &attn_out[(size_t)bh * NN];
        for (int e = tid; e < NN; e += 256) {
            const int i = e / NTOK, j = e - i * NTOK;
            ao[e] = s[i * 56 + j];
        }
    }

    if (tid < 200) {
        const int ip = tid >> 3, d4 = tid & 7;
        const int i0 = ip * 2;
        float4 a0 = make_float4(0.f, 0.f, 0.f, 0.f);
        float4 a1 = make_float4(0.f, 0.f, 0.f, 0.f);
        const float* s0 = &s[i0 * 56];
        const bool two = (i0 + 1 < NTOK);
#pragma unroll
        for (int j = 0; j < NTOK; j++) {
            const float4 vv = vs[j * 8 + d4];
            const float p0 = s0[j];
            a0.x += p0 * vv.x; a0.y += p0 * vv.y;
            a0.z += p0 * vv.z; a0.w += p0 * vv.w;
            const float p1 = two ? s0[56 + j] : 0.f;
            a1.x += p1 * vv.x; a1.y += p1 * vv.y;
            a1.z += p1 * vv.z; a1.w += p1 * vv.w;
        }
        *reinterpret_cast<float4*>(&g_ctx[(row0 + i0) * DIM + qoff + d4 * 4]) = a0;
        if (two)
            *reinterpret_cast<float4*>(&g_ctx[(row0 + i0 + 1) * DIM + qoff + d4 * 4]) = a1;
    }
}

extern "C" void kernel_launch(void* const* d_in, const int* in_sizes, int n_in,
                              void* d_out, int out_size)
{
    const float* x      = (const float*)d_in[0];
    const float* mask   = (const float*)d_in[1];
    const float* qkv_w  = (const float*)d_in[2];
    const float* qkv_b  = (const float*)d_in[3];
    const float* proj_w = (const float*)d_in[4];
    const float* proj_b = (const float*)d_in[5];
    const float* rpb    = (const float*)d_in[6];
    const int*   relidx = (const int*)d_in[7];
    float* out = (float*)d_out;

    const long out_elems  = (long)M_ROWS * DIM;                 // 38,535,168
    const long attn_elems = (long)B_TOT * NHEAD * NN;           // 59,006,976
    const int write_attn = ((long)out_size >= out_elems + attn_elems) ? 1 : 0;
    float* attn_out = out + out_elems;

    // 0) bias+mask table
    bm_kernel<<<NWIN * NHEAD, 256>>>(mask, rpb, relidx);

    // 1) QKV GEMM: [200704,192] @ [192,576] (bf16x3, double-buffered)
    qkv_gemm_kernel<<<dim3(QKV_N / 64, M_ROWS / 128), 256>>>(x, qkv_w, qkv_b);

    // 2) fused window attention
    attn_kernel<<<B_TOT * NHEAD, 256>>>(attn_out, write_attn);

    // 3) projection: [200704,192] @ [192,192] (bf16x3, double-buffered)
    proj_gemm_kernel<<<dim3(DIM / 64, M_ROWS / 128), 256>>>(proj_w, proj_b, out);
}

// round 13
// speedup vs baseline: 1.0449x; 1.0161x over previous
#include <cuda_runtime.h>
#include <cuda_bf16.h>
#include <math.h>
#include <stdint.h>

#define B_TOT   4096
#define NWIN    64
#define NTOK    49
#define DIM     192
#define NHEAD   6
#define HDIM    32
#define M_ROWS  (B_TOT * NTOK)     /* 200704 */
#define QKV_N   576
#define NN      (NTOK * NTOK)      /* 2401 */

// Scratch (no cudaMalloc allowed); referenced directly from kernels so that
// kernel_launch contains ONLY kernel launches (trivially graph-capturable).
__device__ float g_qkv[(size_t)M_ROWS * QKV_N];          // 462 MB
__device__ float g_ctx[(size_t)M_ROWS * DIM];            // 154 MB
__device__ float g_bm[(size_t)NWIN * NHEAD * NN];        // 3.7 MB bias+mask

// ---------------------------------------------------------------------------
// Precompute bm[(mb*NHEAD+h)][e] = rpb[rel_idx[e]*NHEAD+h] + mask[mb][e]
// ---------------------------------------------------------------------------
__global__ __launch_bounds__(256)
void bm_kernel(const float* __restrict__ mask,
               const float* __restrict__ rpb_table,
               const int*   __restrict__ rel_idx)
{
    const int mb = blockIdx.x / NHEAD;
    const int h  = blockIdx.x % NHEAD;
    float* dst = &g_bm[(size_t)blockIdx.x * NN];
    const float* msk = &mask[(size_t)mb * NN];
    for (int e = threadIdx.x; e < NN; e += 256)
        dst[e] = rpb_table[rel_idx[e] * NHEAD + h] + msk[e];
}

// ---------------------------------------------------------------------------
// bf16x3 tensor-core GEMM with INTERLEAVED hi/lo smem ({hi,lo} uint2 pairs):
// every fragment load is one LDS.64, every split store one STS.64.
// C[M,N] = A[M,K] @ W^T + bias, W row-major [N,K].
// BM=128, BN=64, BK=16, 256 threads (8 warps, 4x2 grid of 32x32 warp tiles).
// ---------------------------------------------------------------------------
__device__ __forceinline__ uint32_t pack_bf16x2(float x, float y) {
    __nv_bfloat162 t = __floats2bfloat162_rn(x, y);   // x -> low 16 bits
    return *reinterpret_cast<uint32_t*>(&t);
}

__device__ __forceinline__ void mma_bf16(float* d, const uint32_t* a, const uint32_t* b) {
    asm volatile(
        "mma.sync.aligned.m16n8k16.row.col.f32.bf16.bf16.f32 "
        "{%0,%1,%2,%3}, {%4,%5,%6,%7}, {%8,%9}, {%0,%1,%2,%3};"
        : "+f"(d[0]), "+f"(d[1]), "+f"(d[2]), "+f"(d[3])
        : "r"(a[0]), "r"(a[1]), "r"(a[2]), "r"(a[3]), "r"(b[0]), "r"(b[1]));
}

// Row stride in 32-bit words: 16 data words ({hi,lo}x8 cols) + 24 pad = 40.
// RS8 = 20 ≡ 4 (mod 16)  =>  all LDS.64 fragment phases conflict-free.
#define RS 40

__device__ __forceinline__
void gemm_bf16x3_body(const float* __restrict__ A,
                      const float* __restrict__ W,
                      const float* __restrict__ bias,
                      float* __restrict__ C,
                      int M, int N, int K)
{
    __shared__ uint32_t Ahl[128 * RS];   // 20 KB
    __shared__ uint32_t Bhl[64 * RS];    // 10 KB

    const int tid  = threadIdx.x;
    const int warp = tid >> 5;
    const int lane = tid & 31;
    const int wm   = warp >> 1;        // 0..3 -> m offset wm*32
    const int wn   = warp & 1;         // 0..1 -> n offset wn*32
    const int lr   = lane >> 2;        // 0..7
    const int lc   = lane & 3;         // 0..3
    const int r0   = blockIdx.y * 128;
    const int c0   = blockIdx.x * 64;

    // global load indices
    const int ar = tid >> 1;           // A row 0..127
    const int ac = (tid & 1) * 8;      // A col (floats) 0 or 8
    const int br = tid >> 2;           // B row 0..63
    const int bc = (tid & 3) * 4;      // B col (floats) 0,4,8,12

    const float* Ag = &A[(size_t)(r0 + ar) * K + ac];
    const float* Wg = &W[(size_t)(c0 + br) * K + bc];

    float acc[2][4][4];
#pragma unroll
    for (int mt = 0; mt < 2; mt++)
#pragma unroll
        for (int nt = 0; nt < 4; nt++)
#pragma unroll
            for (int r = 0; r < 4; r++) acc[mt][nt][r] = 0.f;

    // prologue prefetch (tile 0)
    float ap[8], bp[4];
    {
        const float4 a0 = *reinterpret_cast<const float4*>(Ag);
        const float4 a1 = *reinterpret_cast<const float4*>(Ag + 4);
        ap[0]=a0.x; ap[1]=a0.y; ap[2]=a0.z; ap[3]=a0.w;
        ap[4]=a1.x; ap[5]=a1.y; ap[6]=a1.z; ap[7]=a1.w;
        const float4 b0 = *reinterpret_cast<const float4*>(Wg);
        bp[0]=b0.x; bp[1]=b0.y; bp[2]=b0.z; bp[3]=b0.w;
    }

    for (int k0 = 0; k0 < K; k0 += 16) {
        // split hi/lo, pack bf16x2, store interleaved {hi,lo} as STS.64
#pragma unroll
        for (int i = 0; i < 4; i++) {
            const float f0 = ap[2 * i], f1 = ap[2 * i + 1];
            const float h0 = __bfloat162float(__float2bfloat16_rn(f0));
            const float h1 = __bfloat162float(__float2bfloat16_rn(f1));
            const int col = ac / 2 + i;     // bf16x2 word column 0..7
            *reinterpret_cast<uint2*>(&Ahl[ar * RS + col * 2]) =
                make_uint2(pack_bf16x2(h0, h1), pack_bf16x2(f0 - h0, f1 - h1));
        }
#pragma unroll
        for (int i = 0; i < 2; i++) {
            const float f0 = bp[2 * i], f1 = bp[2 * i + 1];
            const float h0 = __bfloat162float(__float2bfloat16_rn(f0));
            const float h1 = __bfloat162float(__float2bfloat16_rn(f1));
            const int col = bc / 2 + i;
            *reinterpret_cast<uint2*>(&Bhl[br * RS + col * 2]) =
                make_uint2(pack_bf16x2(h0, h1), pack_bf16x2(f0 - h0, f1 - h1));
        }
        __syncthreads();

        // prefetch next tile while MMAs below execute
        if (k0 + 16 < K) {
            const float4 a0 = *reinterpret_cast<const float4*>(Ag + k0 + 16);
            const float4 a1 = *reinterpret_cast<const float4*>(Ag + k0 + 20);
            ap[0]=a0.x; ap[1]=a0.y; ap[2]=a0.z; ap[3]=a0.w;
            ap[4]=a1.x; ap[5]=a1.y; ap[6]=a1.z; ap[7]=a1.w;
            const float4 b0 = *reinterpret_cast<const float4*>(Wg + k0 + 16);
            bp[0]=b0.x; bp[1]=b0.y; bp[2]=b0.z; bp[3]=b0.w;
        }

        // fragment loads: 16 LDS.64 per warp, conflict-free
        uint32_t ah[2][4], al[2][4], bh[4][2], bl[4][2];
#pragma unroll
        for (int mt = 0; mt < 2; mt++) {
            const int rbase = (wm * 32 + mt * 16 + lr) * RS;
            const uint2 p00 = *reinterpret_cast<const uint2*>(&Ahl[rbase + lc * 2]);
            const uint2 p10 = *reinterpret_cast<const uint2*>(&Ahl[rbase + 8 * RS + lc * 2]);
            const uint2 p01 = *reinterpret_cast<const uint2*>(&Ahl[rbase + (lc + 4) * 2]);
            const uint2 p11 = *reinterpret_cast<const uint2*>(&Ahl[rbase + 8 * RS + (lc + 4) * 2]);
            ah[mt][0] = p00.x; al[mt][0] = p00.y;
            ah[mt][1] = p10.x; al[mt][1] = p10.y;
            ah[mt][2] = p01.x; al[mt][2] = p01.y;
            ah[mt][3] = p11.x; al[mt][3] = p11.y;
        }
#pragma unroll
        for (int nt = 0; nt < 4; nt++) {
            const int rbase = (wn * 32 + nt * 8 + lr) * RS;
            const uint2 q0 = *reinterpret_cast<const uint2*>(&Bhl[rbase + lc * 2]);
            const uint2 q1 = *reinterpret_cast<const uint2*>(&Bhl[rbase + (lc + 4) * 2]);
            bh[nt][0] = q0.x; bl[nt][0] = q0.y;
            bh[nt][1] = q1.x; bl[nt][1] = q1.y;
        }

#pragma unroll
        for (int mt = 0; mt < 2; mt++)
#pragma unroll
            for (int nt = 0; nt < 4; nt++) {
                mma_bf16(acc[mt][nt], ah[mt], bl[nt]);   // hi*lo
                mma_bf16(acc[mt][nt], al[mt], bh[nt]);   // lo*hi
                mma_bf16(acc[mt][nt], ah[mt], bh[nt]);   // hi*hi
            }
        __syncthreads();
    }

    // epilogue
#pragma unroll
    for (int mt = 0; mt < 2; mt++) {
        const int row = r0 + wm * 32 + mt * 16 + lr;
#pragma unroll
        for (int nt = 0; nt < 4; nt++) {
            const int col = c0 + wn * 32 + nt * 8 + lc * 2;
            const float b0v = bias[col], b1v = bias[col + 1];
            float2 s0, s1;
            s0.x = acc[mt][nt][0] + b0v; s0.y = acc[mt][nt][1] + b1v;
            s1.x = acc[mt][nt][2] + b0v; s1.y = acc[mt][nt][3] + b1v;
            *reinterpret_cast<float2*>(&C[(size_t)row * N + col])       = s0;
            *reinterpret_cast<float2*>(&C[(size_t)(row + 8) * N + col]) = s1;
        }
    }
}

// Wrappers referencing __device__ globals directly (no symbol lookups on host)
__global__ __launch_bounds__(256)
void qkv_gemm_kernel(const float* __restrict__ x,
                     const float* __restrict__ qkv_w,
                     const float* __restrict__ qkv_b)
{
    gemm_bf16x3_body(x, qkv_w, qkv_b, g_qkv, M_ROWS, QKV_N, DIM);
}

__global__ __launch_bounds__(256)
void proj_gemm_kernel(const float* __restrict__ proj_w,
                      const float* __restrict__ proj_b,
                      float* __restrict__ out)
{
    gemm_bf16x3_body(g_ctx, proj_w, proj_b, out, M_ROWS, DIM, DIM);
}

// ---------------------------------------------------------------------------
// Fused attention (proven): one block per (window b, head h).
// ---------------------------------------------------------------------------
#define QPAD 52

__global__ __launch_bounds__(256)
void attn_kernel(float* __restrict__ attn_out, int write_attn)
{
    const int bh = blockIdx.x;
    const int b  = bh / NHEAD;
    const int h  = bh % NHEAD;
    const int tid = threadIdx.x;
    const int mb = b % NWIN;

    __shared__ float4 qs[QPAD * 9];
    __shared__ float4 ksT4[8 * QPAD];
    __shared__ float4 vs[NTOK * 8];
    __shared__ float  s[NTOK * 56];

    const size_t row0 = (size_t)b * NTOK;
    const int qoff = h * HDIM;
    const float scale = 0.1767766952966369f;

    for (int e = tid; e < QPAD * 8; e += 256) {
        const int i = e >> 3, c = e & 7;
        if (i < NTOK) {
            const size_t base = (row0 + i) * QKV_N + qoff + c * 4;
            float4 qv = *reinterpret_cast<const float4*>(&g_qkv[base]);
            qv.x *= scale; qv.y *= scale; qv.z *= scale; qv.w *= scale;
            qs[i * 9 + c] = qv;
            ksT4[c * QPAD + i] = *reinterpret_cast<const float4*>(&g_qkv[base + DIM]);
            vs[i * 8 + c] = *reinterpret_cast<const float4*>(&g_qkv[base + 2 * DIM]);
        } else {
            const float4 z = make_float4(0.f, 0.f, 0.f, 0.f);
            qs[i * 9 + c] = z;
            ksT4[c * QPAD + i] = z;
        }
    }
    __syncthreads();

    const float* bm = &g_bm[(size_t)(mb * NHEAD + h) * NN];
    if (tid < 169) {
        const int ti = tid / 13, tj = tid % 13;
        const int i0 = ti * 4, j0 = tj * 4;
        float acc[4][4];
#pragma unroll
        for (int u = 0; u < 4; u++)
#pragma unroll
            for (int v = 0; v < 4; v++) acc[u][v] = 0.f;
#pragma unroll
        for (int c = 0; c < 8; c++) {
            float4 qv[4], kv[4];
#pragma unroll
            for (int u = 0; u < 4; u++) qv[u] = qs[(i0 + u) * 9 + c];
#pragma unroll
            for (int v = 0; v < 4; v++) kv[v] = ksT4[c * QPAD + j0 + v];
#pragma unroll
            for (int u = 0; u < 4; u++)
#pragma unroll
                for (int v = 0; v < 4; v++)
                    acc[u][v] += qv[u].x * kv[v].x + qv[u].y * kv[v].y
                               + qv[u].z * kv[v].z + qv[u].w * kv[v].w;
        }
#pragma unroll
        for (int u = 0; u < 4; u++) {
            const int i = i0 + u;
            if (i < NTOK) {
#pragma unroll
                for (int v = 0; v < 4; v++) {
                    const int j = j0 + v;
                    if (j < NTOK)
                        s[i * 56 + j] = acc[u][v] + bm[i * NTOK + j];
                }
            }
        }
    }
    __syncthreads();

    {
        const int row = tid >> 2;
        const int q4  = tid & 3;
        const bool act = (row < NTOK);
        float* rowp = &s[(act ? row : 0) * 56];
        float mx = -1e30f;
        if (act) for (int j = q4; j < NTOK; j += 4) mx = fmaxf(mx, rowp[j]);
        mx = fmaxf(mx, __shfl_xor_sync(0xffffffffu, mx, 1));
        mx = fmaxf(mx, __shfl_xor_sync(0xffffffffu, mx, 2));
        float sum = 0.f;
        if (act) {
            for (int j = q4; j < NTOK; j += 4) {
                const float ev = __expf(rowp[j] - mx);
                rowp[j] = ev;
                sum += ev;
            }
        }
        sum += __shfl_xor_sync(0xffffffffu, sum, 1);
        sum += __shfl_xor_sync(0xffffffffu, sum, 2);
        if (act) {
            const float inv = 1.f / sum;
            for (int j = q4; j < NTOK; j += 4) rowp[j] *= inv;
        }
    }
    __syncthreads();

    if (write_attn) {
        float* ao = &attn_out[(size_t)bh * NN];
        for (int e = tid; e < NN; e += 256) {
            const int i = e / NTOK, j = e - i * NTOK;
            ao[e] = s[i * 56 + j];
        }
    }

    if (tid < 200) {
        const int ip = tid >> 3, d4 = tid & 7;
        const int i0 = ip * 2;
        float4 a0 = make_float4(0.f, 0.f, 0.f, 0.f);
        float4 a1 = make_float4(0.f, 0.f, 0.f, 0.f);
        const float* s0 = &s[i0 * 56];
        const bool two = (i0 + 1 < NTOK);
#pragma unroll
        for (int j = 0; j < NTOK; j++) {
            const float4 vv = vs[j * 8 + d4];
            const float p0 = s0[j];
            a0.x += p0 * vv.x; a0.y += p0 * vv.y;
            a0.z += p0 * vv.z; a0.w += p0 * vv.w;
            const float p1 = two ? s0[56 + j] : 0.f;
            a1.x += p1 * vv.x; a1.y += p1 * vv.y;
            a1.z += p1 * vv.z; a1.w += p1 * vv.w;
        }
        *reinterpret_cast<float4*>(&g_ctx[(row0 + i0) * DIM + qoff + d4 * 4]) = a0;
        if (two)
            *reinterpret_cast<float4*>(&g_ctx[(row0 + i0 + 1) * DIM + qoff + d4 * 4]) = a1;
    }
}

extern "C" void kernel_launch(void* const* d_in, const int* in_sizes, int n_in,
                              void* d_out, int out_size)
{
    const float* x      = (const float*)d_in[0];
    const float* mask   = (const float*)d_in[1];
    const float* qkv_w  = (const float*)d_in[2];
    const float* qkv_b  = (const float*)d_in[3];
    const float* proj_w = (const float*)d_in[4];
    const float* proj_b = (const float*)d_in[5];
    const float* rpb    = (const float*)d_in[6];
    const int*   relidx = (const int*)d_in[7];
    float* out = (float*)d_out;

    const long out_elems  = (long)M_ROWS * DIM;                 // 38,535,168
    const long attn_elems = (long)B_TOT * NHEAD * NN;           // 59,006,976
    const int write_attn = ((long)out_size >= out_elems + attn_elems) ? 1 : 0;
    float* attn_out = out + out_elems;

    // 0) bias+mask table
    bm_kernel<<<NWIN * NHEAD, 256>>>(mask, rpb, relidx);

    // 1) QKV GEMM: [200704,192] @ [192,576] (bf16x3, interleaved hi/lo)
    qkv_gemm_kernel<<<dim3(QKV_N / 64, M_ROWS / 128), 256>>>(x, qkv_w, qkv_b);

    // 2) fused window attention
    attn_kernel<<<B_TOT * NHEAD, 256>>>(attn_out, write_attn);

    // 3) projection: [200704,192] @ [192,192] (bf16x3, interleaved hi/lo)
    proj_gemm_kernel<<<dim3(DIM / 64, M_ROWS / 128), 256>>>(proj_w, proj_b, out);
}